// round 1
// baseline (speedup 1.0000x reference)
#include <cuda_runtime.h>
#include <cuda_bf16.h>
#include <math.h>

// Fixed problem shape (from reference): B=128, S=2048, E=512, H=512.
// Dims are derived at runtime but scratch is sized for this shape.
#define MAX_B 128
#define MAX_S 2048
#define MAX_E 512
#define MAX_H 512

__device__ float g_q[MAX_B * MAX_H];    // q = query @ Wq^T + bq
__device__ float g_v[MAX_B * MAX_E];    // v = q @ Wk   (v[b,e] = sum_h q[b,h] Wk[h,e])
__device__ float g_c[MAX_B];            // c[b] = q[b] . bk
__device__ float g_qk[MAX_B * MAX_S];   // masked, clipped logits

// ---------------------------------------------------------------------------
// C[m,n] = bias[n] + sum_k A[m*K+k] * Bm[n*K+k]   (A @ Bm^T)
// M,N,K multiples of 32.
// ---------------------------------------------------------------------------
__global__ __launch_bounds__(1024) void gemm_abT_kernel(
    const float* __restrict__ A, const float* __restrict__ Bm,
    const float* __restrict__ bias, float* __restrict__ C,
    int M, int N, int K)
{
    __shared__ float As[32][33];
    __shared__ float Bs[32][33];
    int tx = threadIdx.x, ty = threadIdx.y;
    int m = blockIdx.y * 32 + ty;
    int n = blockIdx.x * 32 + tx;
    float acc = 0.0f;
    for (int k0 = 0; k0 < K; k0 += 32) {
        As[ty][tx] = A[m * K + k0 + tx];
        Bs[ty][tx] = Bm[(blockIdx.x * 32 + ty) * K + k0 + tx];
        __syncthreads();
#pragma unroll
        for (int k = 0; k < 32; k++)
            acc += As[ty][k] * Bs[tx][k];
        __syncthreads();
    }
    C[m * N + n] = acc + bias[n];
}

// ---------------------------------------------------------------------------
// C[m,n] = sum_k A[m*K+k] * Bm[k*N+n]   (A @ Bm)
// ---------------------------------------------------------------------------
__global__ __launch_bounds__(1024) void gemm_ab_kernel(
    const float* __restrict__ A, const float* __restrict__ Bm,
    float* __restrict__ C, int M, int N, int K)
{
    __shared__ float As[32][33];
    __shared__ float Bs[32][33];
    int tx = threadIdx.x, ty = threadIdx.y;
    int m = blockIdx.y * 32 + ty;
    int n = blockIdx.x * 32 + tx;
    float acc = 0.0f;
    for (int k0 = 0; k0 < K; k0 += 32) {
        As[ty][tx] = A[m * K + k0 + tx];
        Bs[ty][tx] = Bm[(k0 + ty) * N + blockIdx.x * 32 + tx];
        __syncthreads();
#pragma unroll
        for (int k = 0; k < 32; k++)
            acc += As[ty][k] * Bs[k][tx];
        __syncthreads();
    }
    C[m * N + n] = acc;
}

// ---------------------------------------------------------------------------
// c[b] = sum_h q[b,h] * bk[h]
// ---------------------------------------------------------------------------
__global__ __launch_bounds__(128) void c_kernel(const float* __restrict__ bk, int H)
{
    __shared__ float red[4];
    int b = blockIdx.x;
    float s = 0.0f;
    for (int h = threadIdx.x; h < H; h += 128)
        s += g_q[b * H + h] * bk[h];
#pragma unroll
    for (int off = 16; off; off >>= 1)
        s += __shfl_xor_sync(0xffffffffu, s, off);
    int warp = threadIdx.x >> 5, lane = threadIdx.x & 31;
    if (lane == 0) red[warp] = s;
    __syncthreads();
    if (threadIdx.x == 0)
        g_c[b] = red[0] + red[1] + red[2] + red[3];
}

// ---------------------------------------------------------------------------
// The HBM-bound kernel: logits[b,s] = clip*tanh(target[b,s,:] . v[b] + c[b]),
// then mask==1 -> -inf.  E fixed at 512 (128 float4 per row).
// grid = (S/256, B), block = 256 (8 warps). Each warp handles 32 contiguous s,
// processing 2 rows per iteration for MLP.
// ---------------------------------------------------------------------------
__global__ __launch_bounds__(256) void score_kernel(
    const float* __restrict__ target, const int* __restrict__ mask, int S)
{
    __shared__ float4 vsh[128];   // v[b] as 128 x float4
    int b = blockIdx.y;

    const float4* vp = reinterpret_cast<const float4*>(&g_v[b * 512]);
    for (int i = threadIdx.x; i < 128; i += blockDim.x)
        vsh[i] = vp[i];
    __syncthreads();

    float cb = g_c[b];
    int warp = threadIdx.x >> 5;
    int lane = threadIdx.x & 31;
    int sbase = blockIdx.x * 256 + warp * 32;

    const float4* tb = reinterpret_cast<const float4*>(target) +
                       ((size_t)b * S + sbase) * 128;

    for (int i = 0; i < 32; i += 2) {
        const float4* t0 = tb + (size_t)i * 128;
        const float4* t1 = t0 + 128;
        float a0 = 0.0f, a1 = 0.0f;
#pragma unroll
        for (int j = 0; j < 4; j++) {
            float4 x0 = t0[lane + 32 * j];
            float4 x1 = t1[lane + 32 * j];
            float4 vv = vsh[lane + 32 * j];
            a0 += x0.x * vv.x + x0.y * vv.y + x0.z * vv.z + x0.w * vv.w;
            a1 += x1.x * vv.x + x1.y * vv.y + x1.z * vv.z + x1.w * vv.w;
        }
#pragma unroll
        for (int off = 16; off; off >>= 1) {
            a0 += __shfl_xor_sync(0xffffffffu, a0, off);
            a1 += __shfl_xor_sync(0xffffffffu, a1, off);
        }
        if (lane == 0) {
            int s0 = sbase + i;
            float z0 = 10.0f * tanhf(a0 + cb);
            float z1 = 10.0f * tanhf(a1 + cb);
            if (mask[b * S + s0] == 1)     z0 = -INFINITY;
            if (mask[b * S + s0 + 1] == 1) z1 = -INFINITY;
            g_qk[(size_t)b * S + s0]     = z0;
            g_qk[(size_t)b * S + s0 + 1] = z1;
        }
    }
}

// ---------------------------------------------------------------------------
// Row softmax over S elements. grid = B, block = 512.
// ---------------------------------------------------------------------------
__global__ __launch_bounds__(512) void softmax_kernel(float* __restrict__ out, int S)
{
    __shared__ float red[16];
    __shared__ float bval;
    int b = blockIdx.x;
    int tid = threadIdx.x;
    int warp = tid >> 5, lane = tid & 31;
    const float* row = &g_qk[(size_t)b * S];

    // pass 1: max
    float mx = -INFINITY;
    for (int i = tid; i < S; i += 512)
        mx = fmaxf(mx, row[i]);
#pragma unroll
    for (int off = 16; off; off >>= 1)
        mx = fmaxf(mx, __shfl_xor_sync(0xffffffffu, mx, off));
    if (lane == 0) red[warp] = mx;
    __syncthreads();
    if (tid == 0) {
        float m = red[0];
#pragma unroll
        for (int w = 1; w < 16; w++) m = fmaxf(m, red[w]);
        bval = m;
    }
    __syncthreads();
    float rowmax = bval;
    __syncthreads();

    // pass 2: sum of exp
    float sum = 0.0f;
    for (int i = tid; i < S; i += 512)
        sum += expf(row[i] - rowmax);
#pragma unroll
    for (int off = 16; off; off >>= 1)
        sum += __shfl_xor_sync(0xffffffffu, sum, off);
    if (lane == 0) red[warp] = sum;
    __syncthreads();
    if (tid == 0) {
        float s = 0.0f;
#pragma unroll
        for (int w = 0; w < 16; w++) s += red[w];
        bval = s;
    }
    __syncthreads();
    float inv = 1.0f / bval;

    // pass 3: write
    for (int i = tid; i < S; i += 512)
        out[(size_t)b * S + i] = expf(row[i] - rowmax) * inv;
}

// ---------------------------------------------------------------------------
// Inputs (metadata order): query[B,E], target[B,S,E], mask[B,S],
//                          Wq[H,E], bq[H], Wk[H,E], bk[H]
// Output: alpha[B,S] float32
// ---------------------------------------------------------------------------
extern "C" void kernel_launch(void* const* d_in, const int* in_sizes, int n_in,
                              void* d_out, int out_size)
{
    const float* query  = (const float*)d_in[0];
    const float* target = (const float*)d_in[1];
    const int*   mask   = (const int*)d_in[2];
    const float* Wq     = (const float*)d_in[3];
    const float* bq     = (const float*)d_in[4];
    const float* Wk     = (const float*)d_in[5];
    const float* bk     = (const float*)d_in[6];
    float* out = (float*)d_out;

    int H = in_sizes[4];                      // bq length
    int E = in_sizes[1] / in_sizes[2];        // (B*S*E)/(B*S)
    int B = in_sizes[0] / E;                  // (B*E)/E
    int S = in_sizes[2] / B;                  // (B*S)/B

    float* q_ptr; float* v_ptr;
    cudaGetSymbolAddress((void**)&q_ptr, g_q);
    cudaGetSymbolAddress((void**)&v_ptr, g_v);

    // q = query @ Wq^T + bq  : [B,H]
    {
        dim3 grid(H / 32, B / 32);
        dim3 blk(32, 32);
        gemm_abT_kernel<<<grid, blk>>>(query, Wq, bq, q_ptr, B, H, E);
    }
    // v = q @ Wk : [B,E]
    {
        dim3 grid(E / 32, B / 32);
        dim3 blk(32, 32);
        gemm_ab_kernel<<<grid, blk>>>(q_ptr, Wk, v_ptr, B, E, H);
    }
    // c[b] = q[b] . bk
    c_kernel<<<B, 128>>>(bk, H);

    // logits (HBM-bound pass over target)
    {
        dim3 grid(S / 256, B);
        score_kernel<<<grid, 256>>>(target, mask, S);
    }

    // softmax rows
    softmax_kernel<<<B, 512>>>(out, S);
}

// round 2
// speedup vs baseline: 1.6083x; 1.6083x over previous
#include <cuda_runtime.h>
#include <cuda_bf16.h>
#include <math.h>

// Fixed problem shape (from reference): B=128, S=2048, E=512, H=512.
#define MAX_B 128
#define MAX_S 2048
#define MAX_E 512
#define MAX_H 512
#define SPLITK 4

__device__ float g_q[MAX_B * MAX_H];               // q = query @ Wq^T + bq
__device__ float g_v[MAX_B * MAX_E];               // v = q @ Wk
__device__ float g_c[MAX_B];                       // c[b] = q[b] . bk
__device__ float g_e[MAX_B * MAX_S];               // exp(logit - 10) (0 where masked)
__device__ float g_sum[MAX_B];                     // row sums of g_e
__device__ float g_part[SPLITK * MAX_B * MAX_H];   // split-K partials

// ---------------------------------------------------------------------------
// Split-K register-tiled GEMM. Block tile 32(M) x 64(N), thread tile 2x4,
// 256 threads, k-tile 32, grid (N/64, M/32, SPLITK).
// TRANSB=1: C = A @ Bm^T   (Bm is [N,K] row-major)
// TRANSB=0: C = A @ Bm     (Bm is [K,N] row-major)
// Writes partial sums into Cpart[kidx * M*N + ...].
// ---------------------------------------------------------------------------
template <int TRANSB>
__global__ __launch_bounds__(256) void gemm_split_kernel(
    const float* __restrict__ A, const float* __restrict__ Bm,
    float* __restrict__ Cpart, int M, int N, int K)
{
    __shared__ float As[32][33];
    __shared__ float Bs[32][65];
    int tid = threadIdx.x;
    int m0 = blockIdx.y * 32;
    int n0 = blockIdx.x * 64;
    int kidx = blockIdx.z;
    int kbeg = kidx * (K / SPLITK);
    int kend = kbeg + (K / SPLITK);

    int tx = tid & 15;        // 16 col groups of 4
    int ty = tid >> 4;        // 16 row groups of 2
    float acc[2][4] = {};

    for (int k0 = kbeg; k0 < kend; k0 += 32) {
        // As: 32x32 floats = 256 float4, one per thread
        {
            int r = tid >> 3;
            int kq = (tid & 7) * 4;
            float4 a = *(const float4*)&A[(size_t)(m0 + r) * K + k0 + kq];
            As[r][kq] = a.x; As[r][kq + 1] = a.y; As[r][kq + 2] = a.z; As[r][kq + 3] = a.w;
        }
        if (TRANSB) {
            // Bm[n*K + k] -> Bs[kk][n]
#pragma unroll
            for (int t = 0; t < 2; t++) {
                int idx = tid + t * 256;
                int n = idx >> 3;
                int kq = (idx & 7) * 4;
                float4 v = *(const float4*)&Bm[(size_t)(n0 + n) * K + k0 + kq];
                Bs[kq][n] = v.x; Bs[kq + 1][n] = v.y; Bs[kq + 2][n] = v.z; Bs[kq + 3][n] = v.w;
            }
        } else {
            // Bm[k*N + n] -> Bs[kk][n]
#pragma unroll
            for (int t = 0; t < 2; t++) {
                int idx = tid + t * 256;
                int kk = idx >> 4;
                int nq = (idx & 15) * 4;
                float4 v = *(const float4*)&Bm[(size_t)(k0 + kk) * N + n0 + nq];
                Bs[kk][nq] = v.x; Bs[kk][nq + 1] = v.y; Bs[kk][nq + 2] = v.z; Bs[kk][nq + 3] = v.w;
            }
        }
        __syncthreads();
#pragma unroll
        for (int kk = 0; kk < 32; kk++) {
            float a0 = As[ty * 2][kk];
            float a1 = As[ty * 2 + 1][kk];
            float b0 = Bs[kk][tx * 4];
            float b1 = Bs[kk][tx * 4 + 1];
            float b2 = Bs[kk][tx * 4 + 2];
            float b3 = Bs[kk][tx * 4 + 3];
            acc[0][0] += a0 * b0; acc[0][1] += a0 * b1; acc[0][2] += a0 * b2; acc[0][3] += a0 * b3;
            acc[1][0] += a1 * b0; acc[1][1] += a1 * b1; acc[1][2] += a1 * b2; acc[1][3] += a1 * b3;
        }
        __syncthreads();
    }
#pragma unroll
    for (int r = 0; r < 2; r++)
#pragma unroll
        for (int c = 0; c < 4; c++)
            Cpart[(size_t)kidx * M * N + (size_t)(m0 + ty * 2 + r) * N + n0 + tx * 4 + c] = acc[r][c];
}

// ---------------------------------------------------------------------------
// Reduce SPLITK partials (+ optional bias broadcast over N). N must be pow2.
// ---------------------------------------------------------------------------
__global__ __launch_bounds__(256) void reduce_part_kernel(
    float* __restrict__ C, const float* __restrict__ bias, int M, int N)
{
    int i = blockIdx.x * 256 + threadIdx.x;
    int MN = M * N;
    float s = g_part[i] + g_part[MN + i] + g_part[2 * MN + i] + g_part[3 * MN + i];
    if (bias) s += bias[i & (N - 1)];
    C[i] = s;
}

// ---------------------------------------------------------------------------
// c[b] = q[b].bk ; also zeroes g_sum[b] for the score pass.
// ---------------------------------------------------------------------------
__global__ __launch_bounds__(128) void c_kernel(const float* __restrict__ bk, int H)
{
    __shared__ float red[4];
    int b = blockIdx.x;
    float s = 0.0f;
    for (int h = threadIdx.x; h < H; h += 128)
        s += g_q[b * H + h] * bk[h];
#pragma unroll
    for (int off = 16; off; off >>= 1)
        s += __shfl_xor_sync(0xffffffffu, s, off);
    int warp = threadIdx.x >> 5, lane = threadIdx.x & 31;
    if (lane == 0) red[warp] = s;
    __syncthreads();
    if (threadIdx.x == 0) {
        g_c[b] = red[0] + red[1] + red[2] + red[3];
        g_sum[b] = 0.0f;
    }
}

// ---------------------------------------------------------------------------
// HBM-bound score pass with 2-row software-pipelined prefetch.
// g_e[b,s] = exp(10*tanh(target[b,s,:].v[b] + c[b]) - 10), or 0 if masked.
// Per-warp partial exp-sums atomicAdd into g_sum[b].
// E fixed at 512 (128 float4 per row). grid (S/256, B), 256 threads (8 warps),
// each warp covers 32 consecutive rows.
// ---------------------------------------------------------------------------
__global__ __launch_bounds__(256) void score_kernel(
    const float* __restrict__ target, const int* __restrict__ mask, int S)
{
    int b = blockIdx.y;
    int warp = threadIdx.x >> 5;
    int lane = threadIdx.x & 31;
    int sbase = blockIdx.x * 256 + warp * 32;

    // v[b] chunk for this lane, kept in registers (no smem, no LDS)
    const float4* vp = reinterpret_cast<const float4*>(&g_v[b * 512]);
    float4 v0 = __ldg(vp + lane);
    float4 v1 = __ldg(vp + lane + 32);
    float4 v2 = __ldg(vp + lane + 64);
    float4 v3 = __ldg(vp + lane + 96);
    float cb = g_c[b];

    const float4* tb = reinterpret_cast<const float4*>(target) +
                       ((size_t)b * S + sbase) * 128;
    const int* mrow = mask + (size_t)b * S;
    float* erow = &g_e[(size_t)b * S];

    float4 c0[4], c1[4], n0[4], n1[4];
    // preload rows 0,1
#pragma unroll
    for (int j = 0; j < 4; j++) {
        c0[j] = __ldcs(tb + lane + 32 * j);
        c1[j] = __ldcs(tb + 128 + lane + 32 * j);
    }

    float esum = 0.0f;

#pragma unroll
    for (int i = 0; i < 32; i += 2) {
        // prefetch rows i+2, i+3 while current rows compute/reduce
        if (i + 2 < 32) {
            const float4* t0 = tb + (size_t)(i + 2) * 128;
#pragma unroll
            for (int j = 0; j < 4; j++) {
                n0[j] = __ldcs(t0 + lane + 32 * j);
                n1[j] = __ldcs(t0 + 128 + lane + 32 * j);
            }
        }

        float a0 = c0[0].x * v0.x + c0[0].y * v0.y + c0[0].z * v0.z + c0[0].w * v0.w
                 + c0[1].x * v1.x + c0[1].y * v1.y + c0[1].z * v1.z + c0[1].w * v1.w
                 + c0[2].x * v2.x + c0[2].y * v2.y + c0[2].z * v2.z + c0[2].w * v2.w
                 + c0[3].x * v3.x + c0[3].y * v3.y + c0[3].z * v3.z + c0[3].w * v3.w;
        float a1 = c1[0].x * v0.x + c1[0].y * v0.y + c1[0].z * v0.z + c1[0].w * v0.w
                 + c1[1].x * v1.x + c1[1].y * v1.y + c1[1].z * v1.z + c1[1].w * v1.w
                 + c1[2].x * v2.x + c1[2].y * v2.y + c1[2].z * v2.z + c1[2].w * v2.w
                 + c1[3].x * v3.x + c1[3].y * v3.y + c1[3].z * v3.z + c1[3].w * v3.w;

#pragma unroll
        for (int off = 16; off; off >>= 1) {
            a0 += __shfl_xor_sync(0xffffffffu, a0, off);
            a1 += __shfl_xor_sync(0xffffffffu, a1, off);
        }

        if (lane == 0) {
            int s0 = sbase + i;
            // logit = 10*tanh(a+cb) in (-10,10]; shift by fixed 10 -> exp arg in (-20,0]
            float e0 = (mrow[s0] == 1)     ? 0.0f : expf(10.0f * tanhf(a0 + cb) - 10.0f);
            float e1 = (mrow[s0 + 1] == 1) ? 0.0f : expf(10.0f * tanhf(a1 + cb) - 10.0f);
            erow[s0] = e0;
            erow[s0 + 1] = e1;
            esum += e0 + e1;
        }

#pragma unroll
        for (int j = 0; j < 4; j++) { c0[j] = n0[j]; c1[j] = n1[j]; }
    }

    if (lane == 0)
        atomicAdd(&g_sum[b], esum);
}

// ---------------------------------------------------------------------------
// out[b,s] = g_e[b,s] / g_sum[b]
// ---------------------------------------------------------------------------
__global__ __launch_bounds__(256) void norm_kernel(float* __restrict__ out, int S)
{
    int b = blockIdx.y;
    float inv = 1.0f / g_sum[b];
    int i = blockIdx.x * 256 + threadIdx.x;
    out[(size_t)b * S + i] = g_e[(size_t)b * S + i] * inv;
}

// ---------------------------------------------------------------------------
// Inputs (metadata order): query[B,E], target[B,S,E], mask[B,S],
//                          Wq[H,E], bq[H], Wk[H,E], bk[H]
// Output: alpha[B,S] float32
// ---------------------------------------------------------------------------
extern "C" void kernel_launch(void* const* d_in, const int* in_sizes, int n_in,
                              void* d_out, int out_size)
{
    const float* query  = (const float*)d_in[0];
    const float* target = (const float*)d_in[1];
    const int*   mask   = (const int*)d_in[2];
    const float* Wq     = (const float*)d_in[3];
    const float* bq     = (const float*)d_in[4];
    const float* Wk     = (const float*)d_in[5];
    const float* bk     = (const float*)d_in[6];
    float* out = (float*)d_out;

    int H = in_sizes[4];                      // bq length
    int E = in_sizes[1] / in_sizes[2];        // (B*S*E)/(B*S)
    int B = in_sizes[0] / E;                  // (B*E)/E
    int S = in_sizes[2] / B;                  // (B*S)/B

    float* q_ptr; float* v_ptr; float* part_ptr;
    cudaGetSymbolAddress((void**)&q_ptr, g_q);
    cudaGetSymbolAddress((void**)&v_ptr, g_v);
    cudaGetSymbolAddress((void**)&part_ptr, g_part);

    // q = query @ Wq^T + bq : [B,H]
    {
        dim3 grid(H / 64, B / 32, SPLITK);
        gemm_split_kernel<1><<<grid, 256>>>(query, Wq, part_ptr, B, H, E);
        reduce_part_kernel<<<(B * H) / 256, 256>>>(q_ptr, bq, B, H);
    }
    // v = q @ Wk : [B,E]
    {
        dim3 grid(E / 64, B / 32, SPLITK);
        gemm_split_kernel<0><<<grid, 256>>>(q_ptr, Wk, part_ptr, B, E, H);
        reduce_part_kernel<<<(B * E) / 256, 256>>>(v_ptr, nullptr, B, E);
    }
    // c[b] = q[b].bk ; zero g_sum
    c_kernel<<<B, 128>>>(bk, H);

    // exp(logits) pass over target (HBM-bound) + partial row sums
    {
        dim3 grid(S / 256, B);
        score_kernel<<<grid, 256>>>(target, mask, S);
    }

    // normalize
    {
        dim3 grid(S / 256, B);
        norm_kernel<<<grid, 256>>>(out, S);
    }
}

// round 3
// speedup vs baseline: 1.6150x; 1.0042x over previous
#include <cuda_runtime.h>
#include <cuda_bf16.h>
#include <math.h>

// Fixed problem shape (from reference): B=128, S=2048, E=512, H=512.
#define MAX_B 128
#define MAX_S 2048
#define MAX_E 512
#define MAX_H 512
#define SPLITK 4

__device__ float g_c[MAX_B];                        // c[b] = q[b].bk
__device__ float g_sum[MAX_B];                      // row sums of exp
__device__ float g_part[SPLITK * MAX_B * MAX_H];    // q split-K partials
__device__ float g_part2[SPLITK * MAX_B * MAX_E];   // v split-K partials

// ---------------------------------------------------------------------------
// Split-K register-tiled GEMM. Block tile 32(M) x 64(N), thread tile 2x4,
// 256 threads, k-tile 32, grid (N/64, M/32, SPLITK).
// TRANSB=1: C = A @ Bm^T    (Bm is [N,K] row-major)
// TRANSB=0: C = A @ Bm      (Bm is [K,N] row-major)
// APART=1:  A is itself a SPLITK-partial array (g_part) of an [M,K] matrix;
//           the 4 partials are summed and abias[k] added during the A load.
// Writes partial sums into Cpart[kidx * M*N + ...].
// ---------------------------------------------------------------------------
template <int TRANSB, int APART>
__global__ __launch_bounds__(256) void gemm_split_kernel(
    const float* __restrict__ A, const float* __restrict__ abias,
    const float* __restrict__ Bm, float* __restrict__ Cpart,
    int M, int N, int K)
{
    __shared__ float As[32][33];
    __shared__ float Bs[32][65];
    int tid = threadIdx.x;
    int m0 = blockIdx.y * 32;
    int n0 = blockIdx.x * 64;
    int kidx = blockIdx.z;
    int kbeg = kidx * (K / SPLITK);
    int kend = kbeg + (K / SPLITK);

    int tx = tid & 15;
    int ty = tid >> 4;
    float acc[2][4] = {};

    for (int k0 = kbeg; k0 < kend; k0 += 32) {
        // As: 32x32 floats = 256 float4, one per thread
        {
            int r = tid >> 3;
            int kq = (tid & 7) * 4;
            size_t off = (size_t)(m0 + r) * K + k0 + kq;
            float4 a;
            if (APART) {
                int MK = M * K;
                float4 p0 = *(const float4*)&A[off];
                float4 p1 = *(const float4*)&A[MK + off];
                float4 p2 = *(const float4*)&A[2 * MK + off];
                float4 p3 = *(const float4*)&A[3 * MK + off];
                float4 bb = *(const float4*)&abias[k0 + kq];
                a.x = p0.x + p1.x + p2.x + p3.x + bb.x;
                a.y = p0.y + p1.y + p2.y + p3.y + bb.y;
                a.z = p0.z + p1.z + p2.z + p3.z + bb.z;
                a.w = p0.w + p1.w + p2.w + p3.w + bb.w;
            } else {
                a = *(const float4*)&A[off];
            }
            As[r][kq] = a.x; As[r][kq + 1] = a.y; As[r][kq + 2] = a.z; As[r][kq + 3] = a.w;
        }
        if (TRANSB) {
#pragma unroll
            for (int t = 0; t < 2; t++) {
                int idx = tid + t * 256;
                int n = idx >> 3;
                int kq = (idx & 7) * 4;
                float4 v = *(const float4*)&Bm[(size_t)(n0 + n) * K + k0 + kq];
                Bs[kq][n] = v.x; Bs[kq + 1][n] = v.y; Bs[kq + 2][n] = v.z; Bs[kq + 3][n] = v.w;
            }
        } else {
#pragma unroll
            for (int t = 0; t < 2; t++) {
                int idx = tid + t * 256;
                int kk = idx >> 4;
                int nq = (idx & 15) * 4;
                float4 v = *(const float4*)&Bm[(size_t)(k0 + kk) * N + n0 + nq];
                Bs[kk][nq] = v.x; Bs[kk][nq + 1] = v.y; Bs[kk][nq + 2] = v.z; Bs[kk][nq + 3] = v.w;
            }
        }
        __syncthreads();
#pragma unroll
        for (int kk = 0; kk < 32; kk++) {
            float a0 = As[ty * 2][kk];
            float a1 = As[ty * 2 + 1][kk];
            float b0 = Bs[kk][tx * 4];
            float b1 = Bs[kk][tx * 4 + 1];
            float b2 = Bs[kk][tx * 4 + 2];
            float b3 = Bs[kk][tx * 4 + 3];
            acc[0][0] += a0 * b0; acc[0][1] += a0 * b1; acc[0][2] += a0 * b2; acc[0][3] += a0 * b3;
            acc[1][0] += a1 * b0; acc[1][1] += a1 * b1; acc[1][2] += a1 * b2; acc[1][3] += a1 * b3;
        }
        __syncthreads();
    }
#pragma unroll
    for (int r = 0; r < 2; r++)
#pragma unroll
        for (int c = 0; c < 4; c++)
            Cpart[(size_t)kidx * M * N + (size_t)(m0 + ty * 2 + r) * N + n0 + tx * 4 + c] = acc[r][c];
}

// ---------------------------------------------------------------------------
// c[b] = sum_h (sum_k qpart[k][b,h] + bq[h]) * bk[h] ; also zeroes g_sum[b].
// ---------------------------------------------------------------------------
__global__ __launch_bounds__(128) void c_kernel(
    const float* __restrict__ bq, const float* __restrict__ bk, int H)
{
    __shared__ float red[4];
    int b = blockIdx.x;
    int BH = gridDim.x * H;
    float s = 0.0f;
    for (int h = threadIdx.x; h < H; h += 128) {
        size_t off = (size_t)b * H + h;
        float q = g_part[off] + g_part[BH + off] + g_part[2 * BH + off] +
                  g_part[3 * BH + off] + bq[h];
        s += q * bk[h];
    }
#pragma unroll
    for (int off = 16; off; off >>= 1)
        s += __shfl_xor_sync(0xffffffffu, s, off);
    int warp = threadIdx.x >> 5, lane = threadIdx.x & 31;
    if (lane == 0) red[warp] = s;
    __syncthreads();
    if (threadIdx.x == 0) {
        g_c[b] = red[0] + red[1] + red[2] + red[3];
        g_sum[b] = 0.0f;
    }
}

// ---------------------------------------------------------------------------
// HBM-bound score pass, 2-row software pipeline.
// out[b,s] = exp(10*tanh(target[b,s,:].v[b] + c[b]) - 10), or 0 if masked.
// v[b] is reduced from g_part2 split-K partials at block start (L2-hot).
// Per-warp exp-sums atomicAdd into g_sum[b]. E fixed at 512.
// grid (S/256, B), 256 threads (8 warps), warp covers 32 consecutive rows.
// ---------------------------------------------------------------------------
__global__ __launch_bounds__(256) void score_kernel(
    const float* __restrict__ target, const int* __restrict__ mask,
    float* __restrict__ out, int S)
{
    int b = blockIdx.y;
    int warp = threadIdx.x >> 5;
    int lane = threadIdx.x & 31;
    int sbase = blockIdx.x * 256 + warp * 32;

    // v[b] chunk for this lane: sum of 4 split-K partials, in registers
    const int BE4 = MAX_B * MAX_E / 4;   // float4 stride between partials
    const float4* vp = reinterpret_cast<const float4*>(&g_part2[0]) + b * 128;
    float4 v0, v1, v2, v3;
    {
#pragma unroll
        for (int j = 0; j < 4; j++) {
            float4 p0 = __ldg(vp + lane + 32 * j);
            float4 p1 = __ldg(vp + BE4 + lane + 32 * j);
            float4 p2 = __ldg(vp + 2 * BE4 + lane + 32 * j);
            float4 p3 = __ldg(vp + 3 * BE4 + lane + 32 * j);
            float4 r;
            r.x = p0.x + p1.x + p2.x + p3.x;
            r.y = p0.y + p1.y + p2.y + p3.y;
            r.z = p0.z + p1.z + p2.z + p3.z;
            r.w = p0.w + p1.w + p2.w + p3.w;
            if (j == 0) v0 = r; else if (j == 1) v1 = r;
            else if (j == 2) v2 = r; else v3 = r;
        }
    }
    float cb = g_c[b];

    const float4* tb = reinterpret_cast<const float4*>(target) +
                       ((size_t)b * S + sbase) * 128;
    const int* mrow = mask + (size_t)b * S;
    float* erow = out + (size_t)b * S;

    float4 c0[4], c1[4], n0[4], n1[4];
#pragma unroll
    for (int j = 0; j < 4; j++) {
        c0[j] = __ldcs(tb + lane + 32 * j);
        c1[j] = __ldcs(tb + 128 + lane + 32 * j);
    }

    float esum = 0.0f;

#pragma unroll
    for (int i = 0; i < 32; i += 2) {
        if (i + 2 < 32) {
            const float4* t0 = tb + (size_t)(i + 2) * 128;
#pragma unroll
            for (int j = 0; j < 4; j++) {
                n0[j] = __ldcs(t0 + lane + 32 * j);
                n1[j] = __ldcs(t0 + 128 + lane + 32 * j);
            }
        }

        float a0 = c0[0].x * v0.x + c0[0].y * v0.y + c0[0].z * v0.z + c0[0].w * v0.w
                 + c0[1].x * v1.x + c0[1].y * v1.y + c0[1].z * v1.z + c0[1].w * v1.w
                 + c0[2].x * v2.x + c0[2].y * v2.y + c0[2].z * v2.z + c0[2].w * v2.w
                 + c0[3].x * v3.x + c0[3].y * v3.y + c0[3].z * v3.z + c0[3].w * v3.w;
        float a1 = c1[0].x * v0.x + c1[0].y * v0.y + c1[0].z * v0.z + c1[0].w * v0.w
                 + c1[1].x * v1.x + c1[1].y * v1.y + c1[1].z * v1.z + c1[1].w * v1.w
                 + c1[2].x * v2.x + c1[2].y * v2.y + c1[2].z * v2.z + c1[2].w * v2.w
                 + c1[3].x * v3.x + c1[3].y * v3.y + c1[3].z * v3.z + c1[3].w * v3.w;

#pragma unroll
        for (int off = 16; off; off >>= 1) {
            a0 += __shfl_xor_sync(0xffffffffu, a0, off);
            a1 += __shfl_xor_sync(0xffffffffu, a1, off);
        }

        if (lane == 0) {
            int s0 = sbase + i;
            float e0 = (mrow[s0] == 1)     ? 0.0f : expf(10.0f * tanhf(a0 + cb) - 10.0f);
            float e1 = (mrow[s0 + 1] == 1) ? 0.0f : expf(10.0f * tanhf(a1 + cb) - 10.0f);
            erow[s0] = e0;
            erow[s0 + 1] = e1;
            esum += e0 + e1;
        }

#pragma unroll
        for (int j = 0; j < 4; j++) { c0[j] = n0[j]; c1[j] = n1[j]; }
    }

    if (lane == 0)
        atomicAdd(&g_sum[b], esum);
}

// ---------------------------------------------------------------------------
// In-place: out[b,s] /= g_sum[b]   (vectorized float4)
// ---------------------------------------------------------------------------
__global__ __launch_bounds__(256) void norm_kernel(float* __restrict__ out, int S)
{
    int b = blockIdx.y;
    float inv = 1.0f / g_sum[b];
    int i = blockIdx.x * 256 + threadIdx.x;
    float4* p = reinterpret_cast<float4*>(out + (size_t)b * S) + i;
    float4 v = *p;
    v.x *= inv; v.y *= inv; v.z *= inv; v.w *= inv;
    *p = v;
}

// ---------------------------------------------------------------------------
// Inputs (metadata order): query[B,E], target[B,S,E], mask[B,S],
//                          Wq[H,E], bq[H], Wk[H,E], bk[H]
// Output: alpha[B,S] float32
// ---------------------------------------------------------------------------
extern "C" void kernel_launch(void* const* d_in, const int* in_sizes, int n_in,
                              void* d_out, int out_size)
{
    const float* query  = (const float*)d_in[0];
    const float* target = (const float*)d_in[1];
    const int*   mask   = (const int*)d_in[2];
    const float* Wq     = (const float*)d_in[3];
    const float* bq     = (const float*)d_in[4];
    const float* Wk     = (const float*)d_in[5];
    const float* bk     = (const float*)d_in[6];
    float* out = (float*)d_out;

    int H = in_sizes[4];
    int E = in_sizes[1] / in_sizes[2];
    int B = in_sizes[0] / E;
    int S = in_sizes[2] / B;

    float* part_ptr; float* part2_ptr;
    cudaGetSymbolAddress((void**)&part_ptr, g_part);
    cudaGetSymbolAddress((void**)&part2_ptr, g_part2);

    // q partials: query @ Wq^T  -> g_part
    {
        dim3 grid(H / 64, B / 32, SPLITK);
        gemm_split_kernel<1, 0><<<grid, 256>>>(query, nullptr, Wq, part_ptr, B, H, E);
    }
    // c[b] = (sum q partials + bq).bk ; zero g_sum  (only needs g_part)
    c_kernel<<<B, 128>>>(bq, bk, H);

    // v partials: (q partials summed + bq) @ Wk -> g_part2
    {
        dim3 grid(E / 64, B / 32, SPLITK);
        gemm_split_kernel<0, 1><<<grid, 256>>>(part_ptr, bq, Wk, part2_ptr, B, E, H);
    }

    // exp(logits) over target (HBM-bound), writes e into out, sums into g_sum
    {
        dim3 grid(S / 256, B);
        score_kernel<<<grid, 256>>>(target, mask, out, S);
    }

    // in-place normalize (S/4 float4 per row)
    {
        dim3 grid(S / 1024, B);
        norm_kernel<<<grid, 256>>>(out, S);
    }
}

// round 4
// speedup vs baseline: 2.5273x; 1.5648x over previous
#include <cuda_runtime.h>
#include <cuda_bf16.h>
#include <math.h>

// Fixed problem shape (from reference): B=128, S=2048, E=512, H=512.
#define MAX_B 128
#define MAX_S 2048
#define MAX_E 512
#define MAX_H 512
#define SPLITK 4

__device__ float g_c[MAX_B];                        // c[b] = q[b].bk
__device__ float g_sum[MAX_B];                      // row sums of exp
__device__ unsigned g_cnt[MAX_B];                   // per-batch block completion count
__device__ float g_part[SPLITK * MAX_B * MAX_H];    // q split-K partials
__device__ float g_part2[SPLITK * MAX_B * MAX_E];   // v split-K partials

// ---------------------------------------------------------------------------
// Split-K register-tiled GEMM. Block tile 32(M) x 64(N), thread tile 2x4,
// 256 threads, k-tile 32, grid (N/64, M/32, SPLITK).
// TRANSB=1: C = A @ Bm^T    (Bm is [N,K] row-major)
// TRANSB=0: C = A @ Bm      (Bm is [K,N] row-major)
// APART=1:  A is a SPLITK-partial array of an [M,K] matrix; partials are
//           summed and abias[k] added during the A load.
// ---------------------------------------------------------------------------
template <int TRANSB, int APART>
__global__ __launch_bounds__(256) void gemm_split_kernel(
    const float* __restrict__ A, const float* __restrict__ abias,
    const float* __restrict__ Bm, float* __restrict__ Cpart,
    int M, int N, int K)
{
    __shared__ float As[32][33];
    __shared__ float Bs[32][65];
    int tid = threadIdx.x;
    int m0 = blockIdx.y * 32;
    int n0 = blockIdx.x * 64;
    int kidx = blockIdx.z;
    int kbeg = kidx * (K / SPLITK);
    int kend = kbeg + (K / SPLITK);

    int tx = tid & 15;
    int ty = tid >> 4;
    float acc[2][4] = {};

    for (int k0 = kbeg; k0 < kend; k0 += 32) {
        {
            int r = tid >> 3;
            int kq = (tid & 7) * 4;
            size_t off = (size_t)(m0 + r) * K + k0 + kq;
            float4 a;
            if (APART) {
                int MK = M * K;
                float4 p0 = *(const float4*)&A[off];
                float4 p1 = *(const float4*)&A[MK + off];
                float4 p2 = *(const float4*)&A[2 * MK + off];
                float4 p3 = *(const float4*)&A[3 * MK + off];
                float4 bb = *(const float4*)&abias[k0 + kq];
                a.x = p0.x + p1.x + p2.x + p3.x + bb.x;
                a.y = p0.y + p1.y + p2.y + p3.y + bb.y;
                a.z = p0.z + p1.z + p2.z + p3.z + bb.z;
                a.w = p0.w + p1.w + p2.w + p3.w + bb.w;
            } else {
                a = *(const float4*)&A[off];
            }
            As[r][kq] = a.x; As[r][kq + 1] = a.y; As[r][kq + 2] = a.z; As[r][kq + 3] = a.w;
        }
        if (TRANSB) {
#pragma unroll
            for (int t = 0; t < 2; t++) {
                int idx = tid + t * 256;
                int n = idx >> 3;
                int kq = (idx & 7) * 4;
                float4 v = *(const float4*)&Bm[(size_t)(n0 + n) * K + k0 + kq];
                Bs[kq][n] = v.x; Bs[kq + 1][n] = v.y; Bs[kq + 2][n] = v.z; Bs[kq + 3][n] = v.w;
            }
        } else {
#pragma unroll
            for (int t = 0; t < 2; t++) {
                int idx = tid + t * 256;
                int kk = idx >> 4;
                int nq = (idx & 15) * 4;
                float4 v = *(const float4*)&Bm[(size_t)(k0 + kk) * N + n0 + nq];
                Bs[kk][nq] = v.x; Bs[kk][nq + 1] = v.y; Bs[kk][nq + 2] = v.z; Bs[kk][nq + 3] = v.w;
            }
        }
        __syncthreads();
#pragma unroll
        for (int kk = 0; kk < 32; kk++) {
            float a0 = As[ty * 2][kk];
            float a1 = As[ty * 2 + 1][kk];
            float b0 = Bs[kk][tx * 4];
            float b1 = Bs[kk][tx * 4 + 1];
            float b2 = Bs[kk][tx * 4 + 2];
            float b3 = Bs[kk][tx * 4 + 3];
            acc[0][0] += a0 * b0; acc[0][1] += a0 * b1; acc[0][2] += a0 * b2; acc[0][3] += a0 * b3;
            acc[1][0] += a1 * b0; acc[1][1] += a1 * b1; acc[1][2] += a1 * b2; acc[1][3] += a1 * b3;
        }
        __syncthreads();
    }
#pragma unroll
    for (int r = 0; r < 2; r++)
#pragma unroll
        for (int c = 0; c < 4; c++)
            Cpart[(size_t)kidx * M * N + (size_t)(m0 + ty * 2 + r) * N + n0 + tx * 4 + c] = acc[r][c];
}

// ---------------------------------------------------------------------------
// c[b] = sum_h (sum_k qpart[k][b,h] + bq[h]) * bk[h].
// Also zeroes g_sum[b] and g_cnt[b] for the score pass (graph-replay safe).
// ---------------------------------------------------------------------------
__global__ __launch_bounds__(128) void c_kernel(
    const float* __restrict__ bq, const float* __restrict__ bk, int H)
{
    __shared__ float red[4];
    int b = blockIdx.x;
    int BH = gridDim.x * H;
    float s = 0.0f;
    for (int h = threadIdx.x; h < H; h += 128) {
        size_t off = (size_t)b * H + h;
        float q = g_part[off] + g_part[BH + off] + g_part[2 * BH + off] +
                  g_part[3 * BH + off] + bq[h];
        s += q * bk[h];
    }
#pragma unroll
    for (int off = 16; off; off >>= 1)
        s += __shfl_xor_sync(0xffffffffu, s, off);
    int warp = threadIdx.x >> 5, lane = threadIdx.x & 31;
    if (lane == 0) red[warp] = s;
    __syncthreads();
    if (threadIdx.x == 0) {
        g_c[b] = red[0] + red[1] + red[2] + red[3];
        g_sum[b] = 0.0f;
        g_cnt[b] = 0u;
    }
}

// ---------------------------------------------------------------------------
// Score + softmax pass with masked-row skipping.
// For unmasked s: out[b,s] = exp(10*tanh(target[b,s,:].v[b] + c[b]) - 10);
// masked s get 0. Masked rows' target data is NEVER read (halves DRAM).
// Last block per batch b normalizes the row (threadfence + counter pattern).
// E fixed at 512. grid (S/256, B), 256 threads; warp covers 32 rows.
// ---------------------------------------------------------------------------
__device__ __forceinline__ int poprow(unsigned& rem) {
    if (rem == 0) return -1;
    int r = __ffs(rem) - 1;
    rem &= rem - 1;
    return r;
}

__global__ __launch_bounds__(256, 4) void score_kernel(
    const float* __restrict__ target, const int* __restrict__ mask,
    float* __restrict__ out, int S)
{
    __shared__ float4 vsh[128];
    __shared__ bool lastdone;
    int b = blockIdx.y;
    int tid = threadIdx.x;

    // v[b] reduced from split-K partials into smem
    {
        const int BE4 = MAX_B * MAX_E / 4;
        const float4* vp = reinterpret_cast<const float4*>(&g_part2[0]) + b * 128;
        if (tid < 128) {
            float4 p0 = vp[tid];
            float4 p1 = vp[BE4 + tid];
            float4 p2 = vp[2 * BE4 + tid];
            float4 p3 = vp[3 * BE4 + tid];
            float4 r;
            r.x = p0.x + p1.x + p2.x + p3.x;
            r.y = p0.y + p1.y + p2.y + p3.y;
            r.z = p0.z + p1.z + p2.z + p3.z;
            r.w = p0.w + p1.w + p2.w + p3.w;
            vsh[tid] = r;
        }
    }
    __syncthreads();

    int warp = tid >> 5;
    int lane = tid & 31;
    int sbase = blockIdx.x * 256 + warp * 32;
    float cb = g_c[b];

    const float4* tb = reinterpret_cast<const float4*>(target) +
                       ((size_t)b * S + sbase) * 128;
    const int* mrow = mask + (size_t)b * S;
    float* erow = out + (size_t)b * S;

    // mask ballot over this warp's 32 rows; masked rows -> 0 immediately
    int mv = mrow[sbase + lane];
    bool keep = (mv != 1);
    unsigned bits = __ballot_sync(0xffffffffu, keep);
    if (!keep) erow[sbase + lane] = 0.0f;

    float esum = 0.0f;

#define LOADROW(buf, r) { const float4* t_ = tb + (size_t)(r) * 128;            \
        buf[0] = __ldcs(t_ + lane);       buf[1] = __ldcs(t_ + lane + 32);      \
        buf[2] = __ldcs(t_ + lane + 64);  buf[3] = __ldcs(t_ + lane + 96); }

#define DOTV(buf, a) { a = 0.0f;                                                \
        _Pragma("unroll") for (int j_ = 0; j_ < 4; j_++) {                      \
            float4 x_ = buf[j_]; float4 v_ = vsh[lane + 32 * j_];               \
            a += x_.x * v_.x + x_.y * v_.y + x_.z * v_.z + x_.w * v_.w; } }

#define REDUCE_EMIT(a, r) {                                                     \
        _Pragma("unroll") for (int o_ = 16; o_; o_ >>= 1)                       \
            a += __shfl_xor_sync(0xffffffffu, a, o_);                           \
        if (lane == 0) {                                                        \
            float e_ = expf(10.0f * tanhf(a + cb) - 10.0f);                     \
            erow[sbase + (r)] = e_; esum += e_; } }

    {
        unsigned rem = bits;
        float4 A[4], Bf[4];
        int rA = poprow(rem);
        int rB = poprow(rem);
        if (rA >= 0) LOADROW(A, rA);
        if (rB >= 0) LOADROW(Bf, rB);
        while (rA >= 0) {
            int rn = poprow(rem);
            float a;
            DOTV(A, a);
            if (rn >= 0) LOADROW(A, rn);
            REDUCE_EMIT(a, rA);
            rA = rn;
            if (rB < 0) break;
            rn = poprow(rem);
            DOTV(Bf, a);
            if (rn >= 0) LOADROW(Bf, rn);
            REDUCE_EMIT(a, rB);
            rB = rn;
        }
    }

    if (lane == 0)
        atomicAdd(&g_sum[b], esum);

    // make this thread's out-row stores and sum-contribution device-visible
    __threadfence();
    __syncthreads();
    if (tid == 0) {
        unsigned t = atomicAdd(&g_cnt[b], 1u);
        lastdone = (t == gridDim.x - 1);
    }
    __syncthreads();

    // last block of batch b normalizes the (L2-hot) row
    if (lastdone) {
        __threadfence();
        float inv = 1.0f / g_sum[b];
        float4* rowv = reinterpret_cast<float4*>(out + (size_t)b * S);
        for (int i = tid; i < S / 4; i += 256) {
            float4 x = rowv[i];
            x.x *= inv; x.y *= inv; x.z *= inv; x.w *= inv;
            rowv[i] = x;
        }
    }
}

// ---------------------------------------------------------------------------
// Inputs (metadata order): query[B,E], target[B,S,E], mask[B,S],
//                          Wq[H,E], bq[H], Wk[H,E], bk[H]
// Output: alpha[B,S] float32
// ---------------------------------------------------------------------------
extern "C" void kernel_launch(void* const* d_in, const int* in_sizes, int n_in,
                              void* d_out, int out_size)
{
    const float* query  = (const float*)d_in[0];
    const float* target = (const float*)d_in[1];
    const int*   mask   = (const int*)d_in[2];
    const float* Wq     = (const float*)d_in[3];
    const float* bq     = (const float*)d_in[4];
    const float* Wk     = (const float*)d_in[5];
    const float* bk     = (const float*)d_in[6];
    float* out = (float*)d_out;

    int H = in_sizes[4];
    int E = in_sizes[1] / in_sizes[2];
    int B = in_sizes[0] / E;
    int S = in_sizes[2] / B;

    float* part_ptr; float* part2_ptr;
    cudaGetSymbolAddress((void**)&part_ptr, g_part);
    cudaGetSymbolAddress((void**)&part2_ptr, g_part2);

    // q partials: query @ Wq^T -> g_part
    {
        dim3 grid(H / 64, B / 32, SPLITK);
        gemm_split_kernel<1, 0><<<grid, 256>>>(query, nullptr, Wq, part_ptr, B, H, E);
    }
    // c[b] = (sum q partials + bq).bk ; zero g_sum / g_cnt
    c_kernel<<<B, 128>>>(bq, bk, H);

    // v partials: (q partials summed + bq) @ Wk -> g_part2
    {
        dim3 grid(E / 64, B / 32, SPLITK);
        gemm_split_kernel<0, 1><<<grid, 256>>>(part_ptr, bq, Wk, part2_ptr, B, E, H);
    }

    // fused score + softmax (mask-skipping, last-block normalize)
    {
        dim3 grid(S / 256, B);
        score_kernel<<<grid, 256>>>(target, mask, out, S);
    }
}